// round 6
// baseline (speedup 1.0000x reference)
#include <cuda_runtime.h>

// SmoothRankAP (quick_forward, sigmoid, tau=0.01), B=512. Single fused kernel.
// sigma(x) = 0.5*tanh(x/2)+0.5 with h = scores*50.
//   T_all(i) = sum_j tanh(h_j - h_i)               -> sim_all = 0.5*T_all + 256.5
//   T_pos(i) = sum_j tanh(h_j - h_i) * t_j          -> sim_pos = 0.5*(T_pos - tanh(h_q-h_i) + npos) + 0.5
//   ap[q] = (1/npos) * sum_{i: t=1} sim_pos/sim_all;  out = 1 - mean_q ap
//
// 512 blocks x 256 threads. Warp w owns chunks {2w, 2w+1} of 32 columns and
// enumerates its own positive pairs straight from its ballot masks: no scan,
// no poslist, 3 syncthreads total. Pairs processed as duos for ILP.

static constexpr int BB = 512;

__device__ float        g_ap[BB];
__device__ unsigned int g_ticket = 0;   // reset by last block -> deterministic graph replays

__device__ __forceinline__ float tanh_approx(float x) {
    float y;
    asm("tanh.approx.f32 %0, %1;" : "=f"(y) : "f"(x));
    return y;
}

__global__ __launch_bounds__(256) void smoothap_fused_kernel(
    const float* __restrict__ scores,
    const float* __restrict__ target,
    float* __restrict__ out)
{
    __shared__ float hs[BB];          // scores[q,:] * 50
    __shared__ float ts[BB];          // target[q,:]
    __shared__ float warp_acc[8];
    __shared__ int   is_last_s;

    const int tid  = threadIdx.x;
    const int wid  = tid >> 5;        // 0..7
    const int lane = tid & 31;
    const int q    = blockIdx.x;

    // ---- stage row q ----
    if (tid < 128) {
        float4 v = reinterpret_cast<const float4*>(scores + (size_t)q * BB)[tid];
        hs[4 * tid + 0] = v.x * 50.0f; hs[4 * tid + 1] = v.y * 50.0f;
        hs[4 * tid + 2] = v.z * 50.0f; hs[4 * tid + 3] = v.w * 50.0f;
    } else {
        const int k = tid - 128;
        float4 w = reinterpret_cast<const float4*>(target + (size_t)q * BB)[k];
        ts[4 * k + 0] = w.x; ts[4 * k + 1] = w.y;
        ts[4 * k + 2] = w.z; ts[4 * k + 3] = w.w;
    }
    __syncthreads();   // sync 1

    // ---- per-lane register caches (constant indices only) ----
    float hreg[16], treg[16];
    #pragma unroll
    for (int k = 0; k < 16; ++k) {
        hreg[k] = hs[k * 32 + lane];
        treg[k] = ts[k * 32 + lane];
    }
    const float hq = hs[q];

    // npos = sum(target row) — exact small integer in float
    float fnp;
    {
        float s = 0.0f;
        #pragma unroll
        for (int k = 0; k < 16; ++k) s += treg[k];
        #pragma unroll
        for (int o = 16; o; o >>= 1) s += __shfl_xor_sync(0xffffffffu, s, o);
        fnp = s;
    }

    // ---- this warp's positive masks for chunks 2w, 2w+1 (warp-uniform) ----
    unsigned m0 = __ballot_sync(0xffffffffu, ts[(2 * wid)     * 32 + lane] > 0.5f);
    unsigned m1 = __ballot_sync(0xffffffffu, ts[(2 * wid + 1) * 32 + lane] > 0.5f);
    unsigned long long mm = ((unsigned long long)m1 << 32) | (unsigned long long)m0;
    const int cbase = 2 * wid * 32;

    // ---- enumerate own pairs, two at a time ----
    float acc = 0.0f;   // uniform across lanes
    while (mm) {
        const int b0 = __ffsll(mm) - 1;  mm &= mm - 1;
        const bool two = (mm != 0ull);
        int b1 = b0;
        if (two) { b1 = __ffsll(mm) - 1; mm &= mm - 1; }

        const float hiA = hs[cbase + b0];     // LDS broadcast (uniform)
        const float hiB = hs[cbase + b1];

        float aA = 0.0f, pA = 0.0f, aB = 0.0f, pB = 0.0f;
        #pragma unroll
        for (int k = 0; k < 16; ++k) {
            const float thA = tanh_approx(hreg[k] - hiA);
            const float thB = tanh_approx(hreg[k] - hiB);
            aA += thA; pA = fmaf(thA, treg[k], pA);
            aB += thB; pB = fmaf(thB, treg[k], pB);
        }
        #pragma unroll
        for (int o = 16; o; o >>= 1) {
            aA += __shfl_xor_sync(0xffffffffu, aA, o);
            pA += __shfl_xor_sync(0xffffffffu, pA, o);
            aB += __shfl_xor_sync(0xffffffffu, aB, o);
            pB += __shfl_xor_sync(0xffffffffu, pB, o);
        }
        // uniform epilogue on all lanes (sums are broadcast by xor-reduce)
        const float thqA = tanh_approx(hq - hiA);
        acc += __fdividef(0.5f * (pA - thqA + fnp) + 0.5f, 0.5f * aA + 256.5f);
        if (two) {
            const float thqB = tanh_approx(hq - hiB);
            acc += __fdividef(0.5f * (pB - thqB + fnp) + 0.5f, 0.5f * aB + 256.5f);
        }
    }

    if (lane == 0) warp_acc[wid] = acc;
    __syncthreads();   // sync 2

    if (tid == 0) {
        float g = ((warp_acc[0] + warp_acc[1]) + (warp_acc[2] + warp_acc[3]))
                + ((warp_acc[4] + warp_acc[5]) + (warp_acc[6] + warp_acc[7]));
        g_ap[q] = __fdividef(g, fnp);
        __threadfence();                 // publish before ticket
        unsigned tk = atomicAdd(&g_ticket, 1u);
        is_last_s = (tk == (unsigned)(gridDim.x - 1));
    }
    __syncthreads();   // sync 3

    // ---- last block: deterministic final reduction ----
    if (is_last_s) {
        float v = 0.0f;
        if (tid < 128) {
            float4 r = __ldcg(reinterpret_cast<const float4*>(g_ap) + tid);
            v = (r.x + r.y) + (r.z + r.w);
        }
        #pragma unroll
        for (int o = 16; o; o >>= 1) v += __shfl_xor_sync(0xffffffffu, v, o);
        if (lane == 0) warp_acc[wid] = v;
        __syncthreads();
        if (tid == 0) {
            float s = ((warp_acc[0] + warp_acc[1]) + (warp_acc[2] + warp_acc[3]));
            out[0] = 1.0f - s * (1.0f / (float)BB);
            g_ticket = 0;                // reset for next graph replay
        }
    }
}

extern "C" void kernel_launch(void* const* d_in, const int* in_sizes, int n_in,
                              void* d_out, int out_size)
{
    const float* scores = (const float*)d_in[0];
    const float* target = (const float*)d_in[1];
    smoothap_fused_kernel<<<BB, 256>>>(scores, target, (float*)d_out);
}

// round 7
// speedup vs baseline: 1.2399x; 1.2399x over previous
#include <cuda_runtime.h>

// SmoothRankAP (quick_forward, sigmoid, tau=0.01), B=512. Single fused kernel.
// sigma(x) = 0.5*tanh(x/2)+0.5 with h = scores*50.
//   T_all(i) = sum_j tanh(h_j - h_i)        -> sim_all = 0.5*T_all + 256.5
//   T_pos(i) = sum_j tanh(h_j - h_i) * t_j  -> sim_pos = 0.5*(T_pos - tanh(h_q-h_i) + npos) + 0.5
//   ap[q] = (1/npos) * sum_{i: t=1} sim_pos/sim_all;  out = 1 - mean_q ap
//
// 512 blocks x 256 threads, ZERO smem data staging: each lane register-caches
// the whole row straight from global (coalesced, L1-amplified), hi broadcasts
// via shfl. Tail = ONE packed integer atomic (deterministic), no threadfence.

static constexpr int BB = 512;

// [63:12] fixed-point ap-sum (scale 2^32), [11:0] arrival count. Reset by last block.
__device__ unsigned long long g_accum = 0ull;

__device__ __forceinline__ float tanh_approx(float x) {
    float y;
    asm("tanh.approx.f32 %0, %1;" : "=f"(y) : "f"(x));
    return y;
}

__global__ __launch_bounds__(256) void smoothap_fused_kernel(
    const float* __restrict__ scores,
    const float* __restrict__ target,
    float* __restrict__ out)
{
    __shared__ float warp_acc[8];

    const int tid  = threadIdx.x;
    const int wid  = tid >> 5;        // 0..7
    const int lane = tid & 31;
    const int q    = blockIdx.x;

    const float* __restrict__ srow = scores + (size_t)q * BB;
    const float* __restrict__ trow = target + (size_t)q * BB;

    // ---- direct register cache of the whole row (no smem, no sync) ----
    float hreg[16], treg[16];
    #pragma unroll
    for (int k = 0; k < 16; ++k) {
        hreg[k] = __ldg(srow + k * 32 + lane) * 50.0f;   // coalesced 128B / warp-load
        treg[k] = __ldg(trow + k * 32 + lane);
    }
    const float hq = __ldg(srow + q) * 50.0f;            // broadcast load

    // npos = sum(target row): exact small integer
    float fnp;
    {
        float s = 0.0f;
        #pragma unroll
        for (int k = 0; k < 16; ++k) s += treg[k];
        #pragma unroll
        for (int o = 16; o; o >>= 1) s += __shfl_xor_sync(0xffffffffu, s, o);
        fnp = s;
    }

    // ---- warp w owns columns [64w, 64w+64): reload its 2 chunks (L1 hits) ----
    const int cbase = wid * 64;
    const float hA = __ldg(srow + cbase      + lane) * 50.0f;
    const float hB = __ldg(srow + cbase + 32 + lane) * 50.0f;
    const float tA = __ldg(trow + cbase      + lane);
    const float tB = __ldg(trow + cbase + 32 + lane);

    unsigned m0 = __ballot_sync(0xffffffffu, tA > 0.5f);
    unsigned m1 = __ballot_sync(0xffffffffu, tB > 0.5f);
    unsigned long long mm = ((unsigned long long)m1 << 32) | (unsigned long long)m0;

    // ---- enumerate own positive pairs, two at a time ----
    float acc = 0.0f;   // uniform across lanes after reduces
    while (mm) {
        const int b0 = __ffsll(mm) - 1;  mm &= mm - 1;
        const bool two = (mm != 0ull);
        int b1 = b0;
        if (two) { b1 = __ffsll(mm) - 1; mm &= mm - 1; }

        // broadcast h_i from this warp's own chunk registers
        const float s0a = __shfl_sync(0xffffffffu, hA, b0 & 31);
        const float s0b = __shfl_sync(0xffffffffu, hB, b0 & 31);
        const float hiA = (b0 < 32) ? s0a : s0b;
        const float s1a = __shfl_sync(0xffffffffu, hA, b1 & 31);
        const float s1b = __shfl_sync(0xffffffffu, hB, b1 & 31);
        const float hiB = (b1 < 32) ? s1a : s1b;

        float aA = 0.0f, pA = 0.0f, aB = 0.0f, pB = 0.0f;
        #pragma unroll
        for (int k = 0; k < 16; ++k) {
            const float thA = tanh_approx(hreg[k] - hiA);
            const float thB = tanh_approx(hreg[k] - hiB);
            aA += thA; pA = fmaf(thA, treg[k], pA);
            aB += thB; pB = fmaf(thB, treg[k], pB);
        }
        #pragma unroll
        for (int o = 16; o; o >>= 1) {
            aA += __shfl_xor_sync(0xffffffffu, aA, o);
            pA += __shfl_xor_sync(0xffffffffu, pA, o);
            aB += __shfl_xor_sync(0xffffffffu, aB, o);
            pB += __shfl_xor_sync(0xffffffffu, pB, o);
        }
        const float thqA = tanh_approx(hq - hiA);
        acc += __fdividef(0.5f * (pA - thqA + fnp) + 0.5f, 0.5f * aA + 256.5f);
        if (two) {
            const float thqB = tanh_approx(hq - hiB);
            acc += __fdividef(0.5f * (pB - thqB + fnp) + 0.5f, 0.5f * aB + 256.5f);
        }
    }

    if (lane == 0) warp_acc[wid] = acc;
    __syncthreads();                    // the ONLY block-wide sync

    if (tid == 0) {
        float g = ((warp_acc[0] + warp_acc[1]) + (warp_acc[2] + warp_acc[3]))
                + ((warp_acc[4] + warp_acc[5]) + (warp_acc[6] + warp_acc[7]));
        const float ap = __fdividef(g, fnp);          // ap in [0,1]

        // fixed-point (scale 2^32) + count in low 12 bits; integer sum -> deterministic
        unsigned long long contrib =
            ((unsigned long long)__float2ull_rn(ap * 4294967296.0f) << 12) | 1ull;
        unsigned long long nv = atomicAdd(&g_accum, contrib) + contrib;

        if ((nv & 0xFFFull) == (unsigned long long)BB) {      // I'm the last block
            const double sum_ap = (double)(nv >> 12) * (1.0 / 4294967296.0);
            out[0] = (float)(1.0 - sum_ap * (1.0 / (double)BB));
            atomicExch(&g_accum, 0ull);                       // reset for next replay
        }
    }
}

extern "C" void kernel_launch(void* const* d_in, const int* in_sizes, int n_in,
                              void* d_out, int out_size)
{
    const float* scores = (const float*)d_in[0];
    const float* target = (const float*)d_in[1];
    smoothap_fused_kernel<<<BB, 256>>>(scores, target, (float*)d_out);
}